// round 3
// baseline (speedup 1.0000x reference)
#include <cuda_runtime.h>
#include <cuda_bf16.h>
#include <stdint.h>
#include <math.h>

// ---------------- constants ----------------
#define NB 64
#define NN 1024
#define NCH 256
#define NR 4
#define NK 1024
#define TOTB 10240
#define PADB 10248

#define OFF_HHAT   0LL
#define OFF_ZQ     16777216LL
#define OFF_IND    33554432LL
#define OFF_IDXHAT 33619968LL
#define OFF_VQ     33685504LL
#define OFF_LOGITS 33685505LL
#define OFF_PROBS  33686273LL
#define OFF_MODE   33687041LL

// ---------------- device scratch ----------------
__device__ int     g_expert[NB];
__device__ int     g_phy[NB];
__device__ float   g_std;
__device__ float   g_zsq[NB * NN];
__device__ float   g_cbsq[NR * NK];
__device__ int     g_indices[NB * NN];
__device__ uint8_t g_bits[NB * PADB];
__device__ double  g_sse;

// ---------------- threefry2x32 (JAX 20-round) ----------------
__device__ __forceinline__ uint32_t rotl32(uint32_t x, int r) {
    return (x << r) | (x >> (32 - r));
}
__device__ __forceinline__ void threefry2x32(uint32_t k0, uint32_t k1,
                                             uint32_t x0, uint32_t x1,
                                             uint32_t& o0, uint32_t& o1) {
    uint32_t k2 = k0 ^ k1 ^ 0x1BD11BDAu;
    x0 += k0; x1 += k1;
#define TF_R(a) x0 += x1; x1 = rotl32(x1, a); x1 ^= x0;
#define TF_G(a,b,c,d) TF_R(a) TF_R(b) TF_R(c) TF_R(d)
    TF_G(13, 15, 26, 6)  x0 += k1; x1 += k2 + 1u;
    TF_G(17, 29, 16, 24) x0 += k2; x1 += k0 + 2u;
    TF_G(13, 15, 26, 6)  x0 += k0; x1 += k1 + 3u;
    TF_G(17, 29, 16, 24) x0 += k1; x1 += k2 + 4u;
    TF_G(13, 15, 26, 6)  x0 += k2; x1 += k0 + 5u;
#undef TF_G
#undef TF_R
    o0 = x0; o1 = x1;
}

// JAX random.normal from raw 32 bits (XLA erf_inv f32, Giles polynomial)
__device__ __forceinline__ float jax_normal_from_bits(uint32_t bits) {
    float u1 = __uint_as_float(0x3f800000u | (bits >> 9)) - 1.0f; // [0,1)
    const float lo = __uint_as_float(0xBF7FFFFFu);                // nextafter(-1,0)
    float u = __fadd_rn(__fmul_rn(u1, 2.0f), lo);                 // (hi-lo) rounds to 2.0f
    u = fmaxf(u, lo);
    float x2 = __fmul_rn(u, u);
    float w = -log1pf(-x2);
    float p;
    if (w < 5.0f) {
        w = __fsub_rn(w, 2.5f);
        p = 2.81022636e-08f;
        p = __fmaf_rn(p, w, 3.43273939e-07f);
        p = __fmaf_rn(p, w, -3.5233877e-06f);
        p = __fmaf_rn(p, w, -4.39150654e-06f);
        p = __fmaf_rn(p, w, 0.00021858087f);
        p = __fmaf_rn(p, w, -0.00125372503f);
        p = __fmaf_rn(p, w, -0.00417768164f);
        p = __fmaf_rn(p, w, 0.246640727f);
        p = __fmaf_rn(p, w, 1.50140941f);
    } else {
        w = __fsub_rn(sqrtf(w), 3.0f);
        p = -0.000200214257f;
        p = __fmaf_rn(p, w, 0.000100950558f);
        p = __fmaf_rn(p, w, 0.00134934322f);
        p = __fmaf_rn(p, w, -0.00367342844f);
        p = __fmaf_rn(p, w, 0.00573950773f);
        p = __fmaf_rn(p, w, -0.0076224613f);
        p = __fmaf_rn(p, w, 0.00943887047f);
        p = __fmaf_rn(p, w, 1.00167406f);
        p = __fmaf_rn(p, w, 2.83297682f);
    }
    float ei = __fmul_rn(p, u);
    return __fmul_rn(__uint_as_float(0x3FB504F3u) /* f32 sqrt(2) */, ei);
}

// jax_threefry_partitionable=True stream (modern JAX default):
// element i (size <= 2^32): counter = (0, i); 32-bit output = o0 ^ o1.
__device__ __forceinline__ float gen_normal_part(uint32_t k0, uint32_t k1, uint32_t i) {
    uint32_t o0, o1;
    threefry2x32(k0, k1, 0u, i, o0, o1);
    return jax_normal_from_bits(o0 ^ o1);
}

// ---------------- K1: router MLP + softmax + argmax ----------------
__global__ void __launch_bounds__(128) mlp_kernel(
    const float* __restrict__ phi, const float* __restrict__ w0,
    const float* __restrict__ b0, const float* __restrict__ w1,
    const float* __restrict__ b1, const float* __restrict__ w2,
    const float* __restrict__ b2, const float* __restrict__ noise_var,
    float* __restrict__ out) {
    __shared__ float sphi[512], sh[128], sh2[128], sl[12];
    int b = blockIdx.x, t = threadIdx.x;
    if (b == 0 && t == 0) g_sse = 0.0;
    for (int d = t; d < 512; d += 128) sphi[d] = phi[b * 512 + d];
    __syncthreads();
    float a = 0.f;
    #pragma unroll 8
    for (int d = 0; d < 512; d++) a = __fmaf_rn(sphi[d], w0[d * 128 + t], a);
    sh[t] = fmaxf(__fadd_rn(a, b0[t]), 0.f);
    __syncthreads();
    float a2 = 0.f;
    #pragma unroll 8
    for (int i = 0; i < 128; i++) a2 = __fmaf_rn(sh[i], w1[i * 128 + t], a2);
    sh2[t] = fmaxf(__fadd_rn(a2, b1[t]), 0.f);
    __syncthreads();
    if (t < 12) {
        float l = 0.f;
        for (int i = 0; i < 128; i++) l = __fmaf_rn(sh2[i], w2[i * 12 + t], l);
        l = __fadd_rn(l, b2[t]);
        sl[t] = l;
        out[OFF_LOGITS + b * 12 + t] = l;
    }
    __syncthreads();
    if (t == 0) {
        float mx = sl[0]; int mi = 0;
        for (int j = 1; j < 12; j++) if (sl[j] > mx) { mx = sl[j]; mi = j; }
        float e[12], s = 0.f;
        for (int j = 0; j < 12; j++) { e[j] = expf(__fsub_rn(sl[j], mx)); s = __fadd_rn(s, e[j]); }
        for (int j = 0; j < 12; j++) out[OFF_PROBS + b * 12 + j] = __fdiv_rn(e[j], s);
        out[OFF_MODE + b] = (float)mi;
        g_expert[b] = mi / 3;
        g_phy[b] = mi % 3;
        if (b == 0) g_std = sqrtf(fmaxf(noise_var[0], 0.f));
    }
}

// ---------------- K2: squared row norms ----------------
__global__ void __launch_bounds__(256) sq_kernel(const float* __restrict__ H,
                                                 const float* __restrict__ cb) {
    int warp = (blockIdx.x * blockDim.x + threadIdx.x) >> 5;
    int lane = threadIdx.x & 31;
    const int TOT = NB * NN + NR * NK;
    if (warp >= TOT) return;
    const float* src = (warp < NB * NN) ? (H + (size_t)warp * NCH)
                                        : (cb + (size_t)(warp - NB * NN) * NCH);
    double s = 0.0;
    #pragma unroll
    for (int c = lane; c < NCH; c += 32) {
        float v = src[c];
        s += (double)__fmul_rn(v, v);
    }
    #pragma unroll
    for (int off = 16; off; off >>= 1) s += __shfl_down_sync(0xffffffffu, s, off);
    if (lane == 0) {
        if (warp < NB * NN) g_zsq[warp] = (float)s;
        else g_cbsq[warp - NB * NN] = (float)s;
    }
}

// ---------------- K3: fused distance GEMM + argmin ----------------
#define VQ_BK 32
#define VQ_PAD 132

__global__ void __launch_bounds__(256, 2) vq_kernel(const float* __restrict__ H,
                                                    const float* __restrict__ codebooks) {
    __shared__ float As[VQ_BK][VQ_PAD];
    __shared__ float Bs[VQ_BK][VQ_PAD];

    int tid = threadIdx.x;
    int tx = tid & 15;
    int ty = tid >> 4;
    int row0 = blockIdx.x * 128;
    int b = row0 >> 10;
    int r = g_expert[b];
    const float* zbase = H + (size_t)row0 * NCH;
    const float* cbbase = codebooks + (size_t)r * NK * NCH;
    const float* cbsq = g_cbsq + r * NK;

    float zs[8];
    #pragma unroll
    for (int i = 0; i < 8; i++) zs[i] = g_zsq[row0 + ty * 8 + i];

    float minv[8]; int mini[8];
    #pragma unroll
    for (int i = 0; i < 8; i++) { minv[i] = 3.402823466e+38f; mini[i] = 0; }

    for (int cw0 = 0; cw0 < NK; cw0 += 128) {
        float acc[8][8];
        #pragma unroll
        for (int i = 0; i < 8; i++)
            #pragma unroll
            for (int j = 0; j < 8; j++) acc[i][j] = 0.f;

        float cbs[8];
        #pragma unroll
        for (int j = 0; j < 8; j++) cbs[j] = cbsq[cw0 + tx * 8 + j];

        for (int kt = 0; kt < NCH; kt += VQ_BK) {
            #pragma unroll
            for (int q = 0; q < 4; q++) {
                int l = tid + q * 256;
                int mr = l >> 3;
                int k4 = (l & 7) << 2;
                float4 v = *reinterpret_cast<const float4*>(zbase + (size_t)mr * NCH + kt + k4);
                As[k4 + 0][mr] = v.x; As[k4 + 1][mr] = v.y;
                As[k4 + 2][mr] = v.z; As[k4 + 3][mr] = v.w;
                float4 u = *reinterpret_cast<const float4*>(cbbase + (size_t)(cw0 + mr) * NCH + kt + k4);
                Bs[k4 + 0][mr] = u.x; Bs[k4 + 1][mr] = u.y;
                Bs[k4 + 2][mr] = u.z; Bs[k4 + 3][mr] = u.w;
            }
            __syncthreads();
            #pragma unroll
            for (int kk = 0; kk < VQ_BK; kk++) {
                float4 a0 = *reinterpret_cast<const float4*>(&As[kk][ty * 8]);
                float4 a1 = *reinterpret_cast<const float4*>(&As[kk][ty * 8 + 4]);
                float4 b0v = *reinterpret_cast<const float4*>(&Bs[kk][tx * 8]);
                float4 b1v = *reinterpret_cast<const float4*>(&Bs[kk][tx * 8 + 4]);
                float av[8] = {a0.x, a0.y, a0.z, a0.w, a1.x, a1.y, a1.z, a1.w};
                float bv[8] = {b0v.x, b0v.y, b0v.z, b0v.w, b1v.x, b1v.y, b1v.z, b1v.w};
                #pragma unroll
                for (int i = 0; i < 8; i++)
                    #pragma unroll
                    for (int j = 0; j < 8; j++)
                        acc[i][j] = __fmaf_rn(av[i], bv[j], acc[i][j]);
            }
            __syncthreads();
        }
        #pragma unroll
        for (int i = 0; i < 8; i++) {
            #pragma unroll
            for (int j = 0; j < 8; j++) {
                float s = __fadd_rn(zs[i], cbs[j]);
                float d = __fmaf_rn(-2.0f, acc[i][j], s);
                if (d < minv[i]) { minv[i] = d; mini[i] = cw0 + tx * 8 + j; }
            }
        }
    }

    #pragma unroll
    for (int i = 0; i < 8; i++) {
        float v = minv[i]; int ix = mini[i];
        #pragma unroll
        for (int off = 8; off; off >>= 1) {
            float ov = __shfl_down_sync(0xffffffffu, v, off, 16);
            int oi = __shfl_down_sync(0xffffffffu, ix, off, 16);
            if (ov < v || (ov == v && oi < ix)) { v = ov; ix = oi; }
        }
        if (tx == 0) g_indices[row0 + ty * 8 + i] = ix;
    }
}

// ---------------- K4: z_q gather + straight-through + SSE + indices ----------------
__global__ void __launch_bounds__(256) zq_kernel(const float* __restrict__ H,
                                                 const float* __restrict__ codebooks,
                                                 float* __restrict__ out) {
    __shared__ int sidx[128];
    __shared__ double red[256];
    int blk = blockIdx.x, tid = threadIdx.x;
    int row0 = blk * 128;
    int b = row0 >> 10;
    int r = g_expert[b];
    if (tid < 128) {
        int row = row0 + tid;
        int v = g_indices[row];
        sidx[tid] = v;
        out[OFF_IND + row] = (float)v;
    }
    __syncthreads();
    double acc = 0.0;
    int c = tid;
    for (int i = 0; i < 128; i++) {
        size_t row = (size_t)row0 + i;
        float h = H[row * NCH + c];
        float q = codebooks[((size_t)r * NK + sidx[i]) * NCH + c];
        float dlt = __fsub_rn(q, h);
        out[OFF_ZQ + row * NCH + c] = __fadd_rn(h, dlt);
        float sq = __fmul_rn(dlt, dlt);
        acc += (double)sq;
    }
    red[tid] = acc;
    __syncthreads();
    for (int s = 128; s; s >>= 1) {
        if (tid < s) red[tid] += red[tid + s];
        __syncthreads();
    }
    if (tid == 0) atomicAdd(&g_sse, red[0]);
}

// ---------------- K5: QAM channel (mod + partitionable-threefry noise + demod) ----------------
__global__ void __launch_bounds__(256) channel_kernel() {
    int b = blockIdx.x;
    int m = g_phy[b];
    int bps = (m == 0) ? 2 : (m == 1) ? 4 : 6;
    int n_sym = PADB / bps;
    int mside = (m == 0) ? 2 : (m == 1) ? 4 : 8;
    int M = mside * mside;
    float std_ = g_std;

    __shared__ float cx[64], cy[64];
    __shared__ uint32_t skey[2];
    if (threadIdx.x < M) {
        double mean = (m == 0) ? 2.0 : (m == 1) ? 10.0 : 42.0;
        double norm = sqrt(mean + 1e-9);
        int i = threadIdx.x / mside, j = threadIdx.x % mside;
        cx[threadIdx.x] = (float)((double)(-(mside - 1) + 2 * i) / norm);
        cy[threadIdx.x] = (float)((double)(-(mside - 1) + 2 * j) / norm);
    }
    if (threadIdx.x == 0) {
        uint32_t o0, o1;
        threefry2x32(0u, 42u, 0u, (uint32_t)m, o0, o1); // fold_in(key(42), m)
        skey[0] = o0; skey[1] = o1;
    }
    __syncthreads();
    uint32_t k0 = skey[0], k1 = skey[1];
    const int* idxrow = g_indices + b * NN;
    uint8_t* bitrow = g_bits + b * PADB;

    for (int s = threadIdx.x; s < n_sym; s += 256) {
        int p0 = s * bps;
        int sym = 0;
        for (int j = 0; j < bps; j++) {
            int p = p0 + j;
            int bit = 0;
            if (p < TOTB) bit = (idxrow[p / 10] >> (9 - p % 10)) & 1;
            sym = (sym << 1) | bit;
        }
        float tx0 = cx[sym], tx1 = cy[sym];
        uint32_t i0 = (uint32_t)(b * n_sym + s) * 2u;
        float n0 = gen_normal_part(k0, k1, i0);
        float n1 = gen_normal_part(k0, k1, i0 + 1u);
        // reference: rx = tx + std*noise (mul and add separately rounded)
        float rx0 = __fadd_rn(tx0, __fmul_rn(std_, n0));
        float rx1 = __fadd_rn(tx1, __fmul_rn(std_, n1));
        float best = 3.402823466e+38f; int bi = 0;
        for (int k = 0; k < M; k++) {
            float dx = __fsub_rn(rx0, cx[k]);
            float dy = __fsub_rn(rx1, cy[k]);
            float d = __fadd_rn(__fmul_rn(dx, dx), __fmul_rn(dy, dy));
            if (d < best) { best = d; bi = k; }
        }
        for (int j = 0; j < bps; j++)
            bitrow[p0 + j] = (uint8_t)((bi >> (bps - 1 - j)) & 1);
    }
}

// ---------------- K6: idx_hat recompose + H_hat gather + vq_loss ----------------
__global__ void __launch_bounds__(256) final_kernel(const float* __restrict__ H,
                                                    const float* __restrict__ codebooks,
                                                    float* __restrict__ out) {
    __shared__ int sidx[128];
    int blk = blockIdx.x, tid = threadIdx.x;
    int row0 = blk * 128;
    int b = row0 >> 10;
    int r = g_expert[b];
    if (tid < 128) {
        int row = row0 + tid;
        int n = row & (NN - 1);
        const uint8_t* bt = g_bits + b * PADB + n * 10;
        int v = 0;
        #pragma unroll
        for (int j = 0; j < 10; j++) v = (v << 1) | bt[j];
        if (v > NK - 1) v = NK - 1;
        if (v < 0) v = 0;
        sidx[tid] = v;
        out[OFF_IDXHAT + row] = (float)v;
    }
    __syncthreads();
    int c = tid;
    for (int i = 0; i < 128; i++) {
        size_t row = (size_t)row0 + i;
        float h = H[row * NCH + c];
        float cbv = codebooks[((size_t)r * NK + sidx[i]) * NCH + c];
        out[OFF_HHAT + row * NCH + c] = __fadd_rn(h, __fsub_rn(cbv, h));
    }
    if (blk == 0 && tid == 0) {
        double denom = (double)NB * (double)NN * (double)NCH * (double)NCH;
        out[OFF_VQ] = (float)(1.25 * g_sse / denom);
    }
}

// ---------------- launch ----------------
extern "C" void kernel_launch(void* const* d_in, const int* in_sizes, int n_in,
                              void* d_out, int out_size) {
    const float* H         = (const float*)d_in[0];
    const float* phi       = (const float*)d_in[1];
    const float* w0        = (const float*)d_in[2];
    const float* b0        = (const float*)d_in[3];
    const float* w1        = (const float*)d_in[4];
    const float* b1        = (const float*)d_in[5];
    const float* w2        = (const float*)d_in[6];
    const float* b2        = (const float*)d_in[7];
    const float* codebooks = (const float*)d_in[8];
    const float* noise_var = (const float*)d_in[9];
    float* out = (float*)d_out;

    mlp_kernel<<<NB, 128>>>(phi, w0, b0, w1, b1, w2, b2, noise_var, out);

    int warps = NB * NN + NR * NK;
    sq_kernel<<<(warps + 7) / 8, 256>>>(H, codebooks);

    vq_kernel<<<(NB * NN) / 128, 256>>>(H, codebooks);

    zq_kernel<<<(NB * NN) / 128, 256>>>(H, codebooks, out);

    channel_kernel<<<NB, 256>>>();

    final_kernel<<<(NB * NN) / 128, 256>>>(H, codebooks, out);
}